// round 8
// baseline (speedup 1.0000x reference)
#include <cuda_runtime.h>
#include <cstdint>

#define Nn 64
#define Cc 64
#define Tt 300
#define Vv 25
#define Dd 64
#define NT (Nn*Tt)        // 19200
#define VC (Vv*Cc)        // 1600
#define VD (Vv*Dd)        // 1600
#define TT1 4             // timesteps per k1 block
#define R1 (TT1*Vv)       // 100 rows per block
#define TV (Tt*Vv)        // 7500 floats per (n,d) plane
#define YSTR 101          // ys[d][r] row stride
#define NSLOT 32
#define BN_EPS 1e-5f

// ---- k1 smem layout (float offsets), total 16928 floats = 67712 B ----
#define OFF_SRO 0         // 1600 u16 = 800 floats
#define OFF_BS  800       // 64 floats
#define OFF_MS2 864       // 1600 float2 = 3200 floats
#define OFF_XS  4064      // 6400 floats: xs[kc][tl*25+kv]; ws (4096) overlays later
#define OFF_XM  10464     // 6464 floats: xm[c][v*4+tl] (6400) / ys[d][r] (64*101=6464)
#define SM_TOT  16928

typedef unsigned long long ull;

// Scratch (allocation-free: device globals)
__device__ float          g_y[(size_t)NT*VD];  // y in final (N,D,T,V) layout, pre-BN
__device__ float          g_psum[NSLOT][VD];
__device__ float          g_psq[NSLOT][VD];
__device__ float          g_sclt[Dd*Vv];       // scale [d*25+v]
__device__ float          g_biat[Dd*Vv];       // bias  [d*25+v]
__device__ float2         g_ms2[VC];           // [c*25+v] = (tanh(mask)+1, soff_bits)
__device__ unsigned short g_srco[Dd*Vv];       // [dout*25+vout] = ds*101 + vs

// ---- packed f32x2 helpers (sm_100 family base ISA) ----
__device__ __forceinline__ ull pack2s(float x) {
    ull r; asm("mov.b64 %0, {%1,%1};" : "=l"(r) : "f"(x)); return r;
}
__device__ __forceinline__ void fma2(ull& d, ull a, ull b) {
    asm("fma.rn.f32x2 %0, %1, %2, %0;" : "+l"(d) : "l"(a), "l"(b));
}
__device__ __forceinline__ void add2(ull& d, ull a) {
    asm("add.rn.f32x2 %0, %0, %1;" : "+l"(d) : "l"(a));
}
__device__ __forceinline__ void fma2q(ull& q, ull o) {
    asm("fma.rn.f32x2 %0, %1, %1, %0;" : "+l"(q) : "l"(o));
}
__device__ __forceinline__ float2 unpack2(ull v) {
    float2 f; asm("mov.b64 {%0,%1}, %2;" : "=f"(f.x), "=f"(f.y) : "l"(v)); return f;
}

// ---- prep: tables + zero stats ----
__global__ void kprep(const float* __restrict__ fm,
                      const int* __restrict__ shift_in,
                      const int* __restrict__ shift_out) {
    int idx = blockIdx.x * blockDim.x + threadIdx.x;
    if (idx < NSLOT * VD) {
        (&g_psum[0][0])[idx] = 0.0f;
        (&g_psq[0][0])[idx]  = 0.0f;
    }
    if (idx < VC) {
        int v = idx >> 6, c = idx & 63;
        int k  = shift_in[idx];
        int kv = k >> 6, kc = k & 63;
        // xs offset for tl=0: xs[kc*100 + kv]; step per tl is +25
        g_ms2[c * Vv + v] = make_float2(tanhf(fm[idx]) + 1.0f,
                                        __int_as_float(kc * R1 + kv));
        int so = shift_out[idx];                 // src col for output (vout=v, dout=c)
        int vs = so >> 6, ds = so & 63;
        g_srco[c * Vv + v] = (unsigned short)(ds * YSTR + vs);
    }
}

// ---- k1: stage -> gather+mask tile -> reg GEMM -> bias+stats -> shifted write ----
__global__ void __launch_bounds__(256, 3) k1(const float* __restrict__ x0,
                                             const float* __restrict__ W,
                                             const float* __restrict__ b) {
    extern __shared__ float sm[];
    unsigned short* sro = (unsigned short*)(sm + OFF_SRO);
    float*  bsm  = sm + OFF_BS;
    float2* ms2  = (float2*)(sm + OFF_MS2);
    float*  xs   = sm + OFF_XS;                  // raw slice; ws overlays after P2
    float*  ws   = sm + OFF_XS;
    float*  xm   = sm + OFF_XM;                  // gathered tile; ys overlays after GEMM
    float*  ys   = sm + OFF_XM;

    const int tid = threadIdx.x;
    const int nt0 = blockIdx.x * TT1;
    const int n   = nt0 / Tt;
    const int t0  = nt0 - n * Tt;                // 4 | 300

    // P1: stage raw x slice (float2-coalesced), tables, bias
    {
        const float2* xb2 = (const float2*)(x0 + (size_t)n * Cc * TV + (size_t)t0 * Vv);
        float2* xs2 = (float2*)xs;
        for (int i = tid; i < Cc * (R1 / 2); i += 256) {
            int kc = i / (R1 / 2), c2 = i - kc * (R1 / 2);
            xs2[i] = xb2[kc * (TV / 2) + c2];
        }
    }
    for (int i = tid; i < VC; i += 256) { ms2[i] = g_ms2[i]; sro[i] = g_srco[i]; }
    if (tid < Dd) bsm[tid] = b[tid];
    __syncthreads();

    // P2: build gathered+masked tile xm[c*100 + v*4 + tl]
    for (int i = tid; i < Cc * R1; i += 256) {
        int c  = i / R1;
        int rp = i - c * R1;                     // v*4 + tl
        int v  = rp >> 2;
        int tl = rp & 3;
        float2 mo = ms2[c * Vv + v];
        xm[i] = xs[__float_as_int(mo.y) + tl * Vv] * mo.x;
    }
    __syncthreads();

    // P3: stage W over dead xs
    for (int i = tid; i < Cc * Dd; i += 256) ws[i] = W[i];
    __syncthreads();

    // P4: GEMM. 200 threads: (v = tid>>3, dt = tid&7) -> rows v*4+tl, cols d0..d0+7
    const int v  = tid >> 3;
    const int dt = tid & 7;
    const int d0 = dt * 8;

    ull acc[TT1][4];
    if (tid < 200) {
        #pragma unroll
        for (int tl = 0; tl < TT1; tl++)
            #pragma unroll
            for (int k = 0; k < 4; k++) acc[tl][k] = 0ull;

        const float* xmp = xm + v * 4;
        const float* wsp = ws + d0;
        #pragma unroll 2
        for (int c = 0; c < Cc; c++) {
            float4 xv = *(const float4*)(xmp + c * R1);
            const ulonglong2* wp = (const ulonglong2*)(wsp + c * Dd);
            ulonglong2 wA = wp[0];
            ulonglong2 wB = wp[1];
            ull xa;
            xa = pack2s(xv.x);
            fma2(acc[0][0], xa, wA.x); fma2(acc[0][1], xa, wA.y);
            fma2(acc[0][2], xa, wB.x); fma2(acc[0][3], xa, wB.y);
            xa = pack2s(xv.y);
            fma2(acc[1][0], xa, wA.x); fma2(acc[1][1], xa, wA.y);
            fma2(acc[1][2], xa, wB.x); fma2(acc[1][3], xa, wB.y);
            xa = pack2s(xv.z);
            fma2(acc[2][0], xa, wA.x); fma2(acc[2][1], xa, wA.y);
            fma2(acc[2][2], xa, wB.x); fma2(acc[2][3], xa, wB.y);
            xa = pack2s(xv.w);
            fma2(acc[3][0], xa, wA.x); fma2(acc[3][1], xa, wA.y);
            fma2(acc[3][2], xa, wB.x); fma2(acc[3][3], xa, wB.y);
        }

        // packed bias add
        const ull* bp = (const ull*)(bsm + d0);
        ull b0 = bp[0], b1 = bp[1], b2 = bp[2], b3 = bp[3];
        #pragma unroll
        for (int tl = 0; tl < TT1; tl++) {
            add2(acc[tl][0], b0);
            add2(acc[tl][1], b1);
            add2(acc[tl][2], b2);
            add2(acc[tl][3], b3);
        }
    }

    __syncthreads();   // xm reads complete; ys overlays it

    // P5: stats + stage ys[d][tl*25+v]
    if (tid < 200) {
        ull s2[4], q2[4];
        #pragma unroll
        for (int k = 0; k < 4; k++) { s2[k] = 0ull; q2[k] = 0ull; }

        #pragma unroll
        for (int tl = 0; tl < TT1; tl++) {
            const int rbase = tl * Vv + v;
            #pragma unroll
            for (int k = 0; k < 4; k++) {
                ull o2 = acc[tl][k];
                add2(s2[k], o2);
                fma2q(q2[k], o2);
                float2 f = unpack2(o2);
                ys[(d0 + 2*k    ) * YSTR + rbase] = f.x;
                ys[(d0 + 2*k + 1) * YSTR + rbase] = f.y;
            }
        }

        const int slot = blockIdx.x & (NSLOT - 1);
        const int colb = v * Dd + d0;            // pre-shift (source) column
        #pragma unroll
        for (int k = 0; k < 4; k++) {
            float2 fs = unpack2(s2[k]);
            float2 fq = unpack2(q2[k]);
            atomicAdd(&g_psum[slot][colb + 2*k    ], fs.x);
            atomicAdd(&g_psum[slot][colb + 2*k + 1], fs.y);
            atomicAdd(&g_psq[slot][colb + 2*k    ], fq.x);
            atomicAdd(&g_psq[slot][colb + 2*k + 1], fq.y);
        }
    }
    __syncthreads();

    // P6: shift_out-gathered transposed write: g_y[n][d][t0+tl][vout]
    float* yb = g_y + ((size_t)n * Dd) * TV + t0 * Vv;
    for (int i = tid; i < Dd * R1; i += 256) {
        int d  = i / R1;
        int rr = i - d * R1;                     // tl*25 + vout
        int tl = rr / Vv;
        int vo = rr - tl * Vv;
        float val = ys[(int)sro[d * Vv + vo] + tl * Vv];
        yb[(size_t)d * TV + rr] = val;
    }
}

// ---- k3: reduce slots at src column, fold shift_out/gamma/beta -> tables ----
__global__ void k3(const float* __restrict__ gamma, const float* __restrict__ beta,
                   const int* __restrict__ shift_out) {
    int j = blockIdx.x * blockDim.x + threadIdx.x;
    if (j >= VD) return;
    const int src = shift_out[j];
    float s = 0.0f, q = 0.0f;
    #pragma unroll
    for (int sl = 0; sl < NSLOT; sl++) { s += g_psum[sl][src]; q += g_psq[sl][src]; }
    const float inv_n = 1.0f / (float)NT;
    float mean = s * inv_n;
    float var  = q * inv_n - mean * mean;
    float sc   = gamma[j] * rsqrtf(var + BN_EPS);
    int v = j >> 6, d = j & 63;
    g_sclt[d * Vv + v] = sc;
    g_biat[d * Vv + v] = beta[j] - mean * sc;
}

// ---- k4: pure streaming affine + residual + relu over (n,d) planes ----
__global__ void __launch_bounds__(256) k4(const float* __restrict__ x0,
                                          float* __restrict__ out) {
    __shared__ float4 s4[Vv], b4[Vv];
    const int tid = threadIdx.x;
    const int d = blockIdx.x & 63;

    if (tid < Vv) {
        int m = tid;
        const float* sp = g_sclt + d * Vv;
        const float* bp = g_biat + d * Vv;
        int v0 = (4*m) % 25, v1 = (4*m+1) % 25, v2 = (4*m+2) % 25, v3 = (4*m+3) % 25;
        s4[m] = make_float4(sp[v0], sp[v1], sp[v2], sp[v3]);
        b4[m] = make_float4(bp[v0], bp[v1], bp[v2], bp[v3]);
    }
    __syncthreads();

    const size_t base = (size_t)blockIdx.x * TV;     // (n*64+d)*7500
    const float4* yp = (const float4*)(g_y + base);
    const float4* xp = (const float4*)(x0 + base);
    float4* op = (float4*)(out + base);

    #pragma unroll 2
    for (int i = tid; i < TV / 4; i += 256) {        // 1875 float4
        int m = i % 25;
        float4 y = yp[i];
        float4 x = xp[i];
        float4 s = s4[m];
        float4 bb = b4[m];
        float4 r;
        r.x = fmaxf(fmaf(y.x, s.x, bb.x) + x.x, 0.0f);
        r.y = fmaxf(fmaf(y.y, s.y, bb.y) + x.y, 0.0f);
        r.z = fmaxf(fmaf(y.z, s.z, bb.z) + x.z, 0.0f);
        r.w = fmaxf(fmaf(y.w, s.w, bb.w) + x.w, 0.0f);
        op[i] = r;
    }
}

extern "C" void kernel_launch(void* const* d_in, const int* in_sizes, int n_in,
                              void* d_out, int out_size) {
    const float* x0        = (const float*)d_in[0];
    const float* fm        = (const float*)d_in[1];
    const float* W         = (const float*)d_in[2];
    const float* b         = (const float*)d_in[3];
    const float* gamma     = (const float*)d_in[4];
    const float* beta      = (const float*)d_in[5];
    const int*   shift_in  = (const int*)d_in[6];
    const int*   shift_out = (const int*)d_in[7];
    float* out = (float*)d_out;

    const int smem1 = SM_TOT * 4;                    // 67712 B -> 3 CTAs/SM
    cudaFuncSetAttribute(k1, cudaFuncAttributeMaxDynamicSharedMemorySize, smem1);

    kprep<<<(NSLOT * VD + 255) / 256, 256>>>(fm, shift_in, shift_out);
    k1<<<NT / TT1, 256, smem1>>>(x0, W, b);
    k3<<<(VD + 255) / 256, 256>>>(gamma, beta, shift_out);
    k4<<<Nn * Dd, 256>>>(x0, out);
}

// round 9
// speedup vs baseline: 1.7123x; 1.7123x over previous
#include <cuda_runtime.h>
#include <cstdint>

#define Nn 64
#define Cc 64
#define Tt 300
#define Vv 25
#define Dd 64
#define NT (Nn*Tt)        // 19200
#define VC (Vv*Cc)        // 1600
#define VD (Vv*Dd)        // 1600
#define TT1 5             // timesteps per block
#define R1 (TT1*Vv)       // 125 valid rows (M=128 padded)
#define TV (Tt*Vv)        // 7500
#define ASTR 68           // Asm row stride (floats): bank = 4r+c -> conflict-free frags
#define YS 126            // ys[d][r] row stride
#define NSLOT 32
#define BN_EPS 1e-5f

// ---- kg smem layout (float offsets) ----
#define OFF_SRO 0                 // 1600 u16 = 800 floats
#define OFF_BS  800               // 64 floats
#define OFF_XS  864               // 64*125 = 8000 floats
#define OFF_A   8864              // 128*68 = 8704 floats (u32 tf32)
#define OFF_YS  8864              // ys 64*126 = 8064, overlays Asm (dead after MMA)
#define SM_TOT  (8864 + 8704)     // 17568 floats = 70272 B -> 3 CTAs/SM

typedef uint32_t u32;

// Scratch (allocation-free: device globals)
__device__ float          g_y[(size_t)NT*VD];  // y in final (N,D,T,V) layout, pre-BN
__device__ float          g_psum[NSLOT][VD];
__device__ float          g_psq[NSLOT][VD];
__device__ float          g_sclt[Dd*Vv];       // scale [d*25+v]
__device__ float          g_biat[Dd*Vv];       // bias  [d*25+v]
__device__ float2         g_ms2[VC];           // [c*25+v] = (tanh(mask)+1, soff_bits)
__device__ unsigned short g_srco[Dd*Vv];       // [dout*25+vout] = ds*126 + vs
__device__ float2         g_bfrag[64*32];      // B fragments [(ko*8+no)*32+lane]

__device__ __forceinline__ u32 tf32b(float x) {
    u32 r; asm("cvt.rna.tf32.f32 %0, %1;" : "=r"(r) : "f"(x)); return r;
}
__device__ __forceinline__ void mma8(float* c, const u32* a, u32 b0, u32 b1) {
    asm volatile(
        "mma.sync.aligned.m16n8k8.row.col.f32.tf32.tf32.f32 "
        "{%0,%1,%2,%3}, {%4,%5,%6,%7}, {%8,%9}, {%0,%1,%2,%3};"
        : "+f"(c[0]), "+f"(c[1]), "+f"(c[2]), "+f"(c[3])
        : "r"(a[0]), "r"(a[1]), "r"(a[2]), "r"(a[3]), "r"(b0), "r"(b1));
}

// ---- prep: tables, B fragments, zero stats ----
__global__ void kprep(const float* __restrict__ fm,
                      const int* __restrict__ shift_in,
                      const int* __restrict__ shift_out,
                      const float* __restrict__ W) {
    int idx = blockIdx.x * blockDim.x + threadIdx.x;
    if (idx < NSLOT * VD) {
        (&g_psum[0][0])[idx] = 0.0f;
        (&g_psq[0][0])[idx]  = 0.0f;
    }
    if (idx < VC) {
        int v = idx >> 6, c = idx & 63;
        int k  = shift_in[idx];
        int kv = k >> 6, kc = k & 63;
        g_ms2[c * Vv + v] = make_float2(tanhf(fm[idx]) + 1.0f,
                                        __int_as_float(kc * R1 + kv));
        int so = shift_out[idx];                 // src col for output (vout=v, dout=c)
        int vs = so >> 6, ds = so & 63;
        g_srco[c * Vv + v] = (unsigned short)(ds * YS + vs);
    }
    if (idx < 64 * 32) {
        // B fragment: tile kidx=(ko*8+no), lane: b0=W[k0][n], b1=W[k0+4][n]
        int lane = idx & 31, kidx = idx >> 5;
        int ko = kidx >> 3, no = kidx & 7;
        int t = lane & 3, g = lane >> 2;
        int k0 = ko * 8 + t;
        int n  = no * 8 + g;
        g_bfrag[idx] = make_float2(__uint_as_float(tf32b(W[k0 * Dd + n])),
                                   __uint_as_float(tf32b(W[(k0 + 4) * Dd + n])));
    }
}

// ---- kg: gather+mask -> warp-MMA tf32 -> bias+stats -> shifted transpose write ----
__global__ void __launch_bounds__(256, 3) kg(const float* __restrict__ x0,
                                             const float* __restrict__ b) {
    extern __shared__ float sm[];
    unsigned short* sro = (unsigned short*)(sm + OFF_SRO);
    float* bsm = sm + OFF_BS;
    float* xs  = sm + OFF_XS;
    u32*   As  = (u32*)(sm + OFF_A);
    float* ys  = sm + OFF_YS;                    // overlays Asm after MMA

    const int tid = threadIdx.x;
    const int nt0 = blockIdx.x * TT1;
    const int n   = nt0 / Tt;
    const int t0  = nt0 - n * Tt;                // 5 | 300

    // P1: stage raw slice xs[kc*125 + (tl*25+kv)] + tables
    const float* xb = x0 + (size_t)n * Cc * TV + (size_t)t0 * Vv;
    for (int i = tid; i < Cc * R1; i += 256) {
        int kc = i / R1, col = i - kc * R1;
        xs[i] = xb[(size_t)kc * TV + col];
    }
    for (int i = tid; i < VC; i += 256) sro[i] = g_srco[i];
    if (tid < Dd) bsm[tid] = b[tid];
    __syncthreads();

    // P2: gathered+masked tf32 A tile, Asm[r*68+c]
    for (int i = tid; i < 128 * Cc; i += 256) {
        int r = i >> 6, c = i & 63;
        float val = 0.0f;
        if (r < R1) {
            int tl = r / Vv, v = r - tl * Vv;
            float2 mo = __ldg(&g_ms2[c * Vv + v]);
            val = xs[__float_as_int(mo.y) + tl * Vv] * mo.x;
        }
        As[r * ASTR + c] = tf32b(val);
    }
    __syncthreads();

    // P3: warp MMA. 8 warps: mw = w&3 (M 32-slice), nw = w>>2 (N 32-slice)
    const int lane = tid & 31;
    const int w    = tid >> 5;
    const int mw   = w & 3;
    const int nw   = w >> 2;
    const int g    = lane >> 2;
    const int t    = lane & 3;

    float Cr[2][4][4];
    #pragma unroll
    for (int mt = 0; mt < 2; mt++)
        #pragma unroll
        for (int no = 0; no < 4; no++)
            #pragma unroll
            for (int k = 0; k < 4; k++) Cr[mt][no][k] = 0.0f;

    const float2* bf = g_bfrag + lane;
    #pragma unroll
    for (int ko = 0; ko < 8; ko++) {
        u32 a[2][4];
        #pragma unroll
        for (int mt = 0; mt < 2; mt++) {
            int base = (mw * 32 + mt * 16 + g) * ASTR + ko * 8 + t;
            a[mt][0] = As[base];
            a[mt][1] = As[base + 8 * ASTR];
            a[mt][2] = As[base + 4];
            a[mt][3] = As[base + 8 * ASTR + 4];
        }
        #pragma unroll
        for (int no = 0; no < 4; no++) {
            float2 bb = bf[(ko * 8 + nw * 4 + no) * 32];
            u32 b0 = __float_as_uint(bb.x), b1 = __float_as_uint(bb.y);
            mma8(Cr[0][no], a[0], b0, b1);
            mma8(Cr[1][no], a[1], b0, b1);
        }
    }

    __syncthreads();   // all Asm reads complete; ys overlays it

    // P4: bias + store ys[d*126 + r]
    #pragma unroll
    for (int no = 0; no < 4; no++) {
        const int d0 = nw * 32 + no * 8 + 2 * t;
        const float bi0 = bsm[d0], bi1 = bsm[d0 + 1];
        #pragma unroll
        for (int mt = 0; mt < 2; mt++) {
            int r0 = mw * 32 + mt * 16 + g;
            int r1 = r0 + 8;
            if (r0 < R1) {
                ys[d0 * YS + r0]       = Cr[mt][no][0] + bi0;
                ys[(d0 + 1) * YS + r0] = Cr[mt][no][1] + bi1;
            }
            if (r1 < R1) {
                ys[d0 * YS + r1]       = Cr[mt][no][2] + bi0;
                ys[(d0 + 1) * YS + r1] = Cr[mt][no][3] + bi1;
            }
        }
    }
    __syncthreads();

    // P5: per-column stats (pre-shift columns), 2 atomics per col per block
    {
        const int slot = blockIdx.x & (NSLOT - 1);
        for (int i = tid; i < VD; i += 256) {
            int v = i >> 6, d = i & 63;
            float s = 0.0f, q = 0.0f;
            #pragma unroll
            for (int tl = 0; tl < TT1; tl++) {
                float val = ys[d * YS + tl * Vv + v];
                s += val; q += val * val;
            }
            atomicAdd(&g_psum[slot][i], s);
            atomicAdd(&g_psq[slot][i],  q);
        }
    }

    // P6: shift_out-gathered transposed write: g_y[n][d][t0+tl][vout]
    {
        float* yb = g_y + ((size_t)n * Dd) * TV + t0 * Vv;
        for (int i = tid; i < Dd * R1; i += 256) {
            int d  = i / R1;
            int rr = i - d * R1;                 // tl*25 + vout
            int tl = rr / Vv;
            int vo = rr - tl * Vv;
            float val = ys[(int)sro[d * Vv + vo] + tl * Vv];
            yb[(size_t)d * TV + rr] = val;
        }
    }
}

// ---- k3: reduce slots at src column, fold shift_out/gamma/beta -> tables ----
__global__ void k3(const float* __restrict__ gamma, const float* __restrict__ beta,
                   const int* __restrict__ shift_out) {
    int j = blockIdx.x * blockDim.x + threadIdx.x;
    if (j >= VD) return;
    const int src = shift_out[j];
    float s = 0.0f, q = 0.0f;
    #pragma unroll
    for (int sl = 0; sl < NSLOT; sl++) { s += g_psum[sl][src]; q += g_psq[sl][src]; }
    const float inv_n = 1.0f / (float)NT;
    float mean = s * inv_n;
    float var  = q * inv_n - mean * mean;
    float sc   = gamma[j] * rsqrtf(var + BN_EPS);
    int v = j >> 6, d = j & 63;
    g_sclt[d * Vv + v] = sc;
    g_biat[d * Vv + v] = beta[j] - mean * sc;
}

// ---- k4: pure streaming affine + residual + relu over (n,d) planes ----
__global__ void __launch_bounds__(256) k4(const float* __restrict__ x0,
                                          float* __restrict__ out) {
    __shared__ float4 s4[Vv], b4[Vv];
    const int tid = threadIdx.x;
    const int d = blockIdx.x & 63;

    if (tid < Vv) {
        int m = tid;
        const float* sp = g_sclt + d * Vv;
        const float* bp = g_biat + d * Vv;
        int v0 = (4*m) % 25, v1 = (4*m+1) % 25, v2 = (4*m+2) % 25, v3 = (4*m+3) % 25;
        s4[m] = make_float4(sp[v0], sp[v1], sp[v2], sp[v3]);
        b4[m] = make_float4(bp[v0], bp[v1], bp[v2], bp[v3]);
    }
    __syncthreads();

    const size_t base = (size_t)blockIdx.x * TV;     // (n*64+d)*7500
    const float4* yp = (const float4*)(g_y + base);
    const float4* xp = (const float4*)(x0 + base);
    float4* op = (float4*)(out + base);

    #pragma unroll 2
    for (int i = tid; i < TV / 4; i += 256) {        // 1875 float4
        int m = i % 25;
        float4 y = yp[i];
        float4 x = xp[i];
        float4 s = s4[m];
        float4 bb = b4[m];
        float4 r;
        r.x = fmaxf(fmaf(y.x, s.x, bb.x) + x.x, 0.0f);
        r.y = fmaxf(fmaf(y.y, s.y, bb.y) + x.y, 0.0f);
        r.z = fmaxf(fmaf(y.z, s.z, bb.z) + x.z, 0.0f);
        r.w = fmaxf(fmaf(y.w, s.w, bb.w) + x.w, 0.0f);
        op[i] = r;
    }
}

extern "C" void kernel_launch(void* const* d_in, const int* in_sizes, int n_in,
                              void* d_out, int out_size) {
    const float* x0        = (const float*)d_in[0];
    const float* fm        = (const float*)d_in[1];
    const float* W         = (const float*)d_in[2];
    const float* b         = (const float*)d_in[3];
    const float* gamma     = (const float*)d_in[4];
    const float* beta      = (const float*)d_in[5];
    const int*   shift_in  = (const int*)d_in[6];
    const int*   shift_out = (const int*)d_in[7];
    float* out = (float*)d_out;

    const int smem1 = SM_TOT * 4;                    // 70272 B
    cudaFuncSetAttribute(kg, cudaFuncAttributeMaxDynamicSharedMemorySize, smem1);

    kprep<<<(NSLOT * VD + 255) / 256, 256>>>(fm, shift_in, shift_out, W);
    kg<<<NT / TT1, 256, smem1>>>(x0, b);
    k3<<<(VD + 255) / 256, 256>>>(gamma, beta, shift_out);
    k4<<<Nn * Dd, 256>>>(x0, out);
}

// round 10
// speedup vs baseline: 1.8852x; 1.1010x over previous
#include <cuda_runtime.h>
#include <cstdint>

#define Nn 64
#define Cc 64
#define Tt 300
#define Vv 25
#define Dd 64
#define NT (Nn*Tt)        // 19200
#define VC (Vv*Cc)        // 1600
#define VD (Vv*Dd)        // 1600
#define TT1 5             // timesteps per block
#define R1 (TT1*Vv)       // 125 valid rows (M=128 padded)
#define TV (Tt*Vv)        // 7500
#define YS 126            // ys[d][r] row stride
#define NSLOT 32
#define BN_EPS 1e-5f

// ---- kg smem layout (float offsets) ----
#define OFF_SRO 0                 // 1600 u16 = 800 floats
#define OFF_BS  800               // 64 floats
#define OFF_MS2 864               // 1600 float2 = 3200 floats
#define OFF_XS  4064              // xs 64*125 = 8000 floats; ys 64*126 = 8064 overlays
#define SM_TOT  (4064 + 8064)     // 12128 floats = 48512 B -> 4 CTAs/SM

typedef uint32_t u32;

// Scratch (allocation-free: device globals)
__device__ float          g_y[(size_t)NT*VD];  // y in final (N,D,T,V) layout, pre-BN
__device__ float          g_psum[NSLOT][VD];
__device__ float          g_psq[NSLOT][VD];
__device__ float          g_sclt[Dd*Vv];       // scale [d*25+v]
__device__ float          g_biat[Dd*Vv];       // bias  [d*25+v]
__device__ float2         g_ms2[VC];           // [c*25+v] = (tanh(mask)+1, soff_bits)
__device__ unsigned short g_srco[Dd*Vv];       // [dout*25+vout] = ds*126 + vs
__device__ float2         g_bfrag[64*32];      // B fragments [(ko*8+no)*32+lane]

__device__ __forceinline__ u32 tf32b(float x) {
    u32 r; asm("cvt.rna.tf32.f32 %0, %1;" : "=r"(r) : "f"(x)); return r;
}
__device__ __forceinline__ void mma8(float* c, const u32* a, u32 b0, u32 b1) {
    asm volatile(
        "mma.sync.aligned.m16n8k8.row.col.f32.tf32.tf32.f32 "
        "{%0,%1,%2,%3}, {%4,%5,%6,%7}, {%8,%9}, {%0,%1,%2,%3};"
        : "+f"(c[0]), "+f"(c[1]), "+f"(c[2]), "+f"(c[3])
        : "r"(a[0]), "r"(a[1]), "r"(a[2]), "r"(a[3]), "r"(b0), "r"(b1));
}

// ---- prep: tables, B fragments, zero stats ----
__global__ void kprep(const float* __restrict__ fm,
                      const int* __restrict__ shift_in,
                      const int* __restrict__ shift_out,
                      const float* __restrict__ W) {
    int idx = blockIdx.x * blockDim.x + threadIdx.x;
    if (idx < NSLOT * VD) {
        (&g_psum[0][0])[idx] = 0.0f;
        (&g_psq[0][0])[idx]  = 0.0f;
    }
    if (idx < VC) {
        int v = idx >> 6, c = idx & 63;
        int k  = shift_in[idx];
        int kv = k >> 6, kc = k & 63;
        g_ms2[c * Vv + v] = make_float2(tanhf(fm[idx]) + 1.0f,
                                        __int_as_float(kc * R1 + kv));
        int so = shift_out[idx];                 // src col for output (vout=v, dout=c)
        int vs = so >> 6, ds = so & 63;
        g_srco[c * Vv + v] = (unsigned short)(ds * YS + vs);
    }
    if (idx < 64 * 32) {
        // B fragment: tile kidx=(ko*8+no), lane: b0=W[k0][n], b1=W[k0+4][n]
        int lane = idx & 31, kidx = idx >> 5;
        int ko = kidx >> 3, no = kidx & 7;
        int t = lane & 3, g = lane >> 2;
        int k0 = ko * 8 + t;
        int n  = no * 8 + g;
        g_bfrag[idx] = make_float2(__uint_as_float(tf32b(W[k0 * Dd + n])),
                                   __uint_as_float(tf32b(W[(k0 + 4) * Dd + n])));
    }
}

// ---- kg: direct-gather warp-MMA tf32 -> bias+stats -> shifted transpose write ----
__global__ void __launch_bounds__(256, 4) kg(const float* __restrict__ x0,
                                             const float* __restrict__ b) {
    extern __shared__ float sm[];
    unsigned short* sro = (unsigned short*)(sm + OFF_SRO);
    float*  bsm = sm + OFF_BS;
    float2* ms2 = (float2*)(sm + OFF_MS2);
    float*  xs  = sm + OFF_XS;
    float*  ys  = sm + OFF_XS;                   // overlays xs after MMA

    const int tid = threadIdx.x;
    const int nt0 = blockIdx.x * TT1;
    const int n   = nt0 / Tt;
    const int t0  = nt0 - n * Tt;                // 5 | 300

    // P1: stage raw slice xs[kc*125 + (tl*25+kv)] + tables
    const float* xb = x0 + (size_t)n * Cc * TV + (size_t)t0 * Vv;
    for (int i = tid; i < Cc * R1; i += 256) {
        int kc = i / R1, col = i - kc * R1;
        xs[i] = xb[(size_t)kc * TV + col];
    }
    for (int i = tid; i < VC; i += 256) {
        sro[i] = g_srco[i];
        ms2[i] = g_ms2[i];
    }
    if (tid < Dd) bsm[tid] = b[tid];
    __syncthreads();

    // P2: warp MMA with inline gather. 8 warps: mw = w&3 (M), nw = w>>2 (N)
    const int lane = tid & 31;
    const int w    = tid >> 5;
    const int mw   = w & 3;
    const int nw   = w >> 2;
    const int g    = lane >> 2;
    const int t    = lane & 3;

    // per-row precompute: rows r = mw*32 + mt*16 + h*8 + g
    int  vrow[2][2], xoff[2][2];
    bool okr[2][2];
    #pragma unroll
    for (int mt = 0; mt < 2; mt++)
        #pragma unroll
        for (int h = 0; h < 2; h++) {
            int r = mw * 32 + mt * 16 + h * 8 + g;
            okr[mt][h]  = (r < R1);
            int tl = r / Vv;
            vrow[mt][h] = r - tl * Vv;
            xoff[mt][h] = tl * Vv;
        }

    float Cr[2][4][4];
    #pragma unroll
    for (int mt = 0; mt < 2; mt++)
        #pragma unroll
        for (int no = 0; no < 4; no++)
            #pragma unroll
            for (int k = 0; k < 4; k++) Cr[mt][no][k] = 0.0f;

    const float2* bf = g_bfrag + lane;
    #pragma unroll
    for (int ko = 0; ko < 8; ko++) {
        u32 a[2][4];
        #pragma unroll
        for (int mt = 0; mt < 2; mt++)
            #pragma unroll
            for (int kh = 0; kh < 2; kh++) {
                const int c = ko * 8 + t + kh * 4;
                #pragma unroll
                for (int h = 0; h < 2; h++) {
                    float val = 0.0f;
                    if (okr[mt][h]) {
                        float2 mo = ms2[c * Vv + vrow[mt][h]];
                        val = xs[__float_as_int(mo.y) + xoff[mt][h]] * mo.x;
                    }
                    a[mt][kh * 2 + h] = tf32b(val);
                }
            }
        #pragma unroll
        for (int no = 0; no < 4; no++) {
            float2 bb = bf[(ko * 8 + nw * 4 + no) * 32];
            u32 b0 = __float_as_uint(bb.x), b1 = __float_as_uint(bb.y);
            mma8(Cr[0][no], a[0], b0, b1);
            mma8(Cr[1][no], a[1], b0, b1);
        }
    }

    __syncthreads();   // all xs/ms2 reads complete; ys overlays xs

    // P3: bias + store ys[d*126 + r]
    #pragma unroll
    for (int no = 0; no < 4; no++) {
        const int d0 = nw * 32 + no * 8 + 2 * t;
        const float bi0 = bsm[d0], bi1 = bsm[d0 + 1];
        #pragma unroll
        for (int mt = 0; mt < 2; mt++) {
            int r0 = mw * 32 + mt * 16 + g;
            int r1 = r0 + 8;
            if (r0 < R1) {
                ys[d0 * YS + r0]       = Cr[mt][no][0] + bi0;
                ys[(d0 + 1) * YS + r0] = Cr[mt][no][1] + bi1;
            }
            if (r1 < R1) {
                ys[d0 * YS + r1]       = Cr[mt][no][2] + bi0;
                ys[(d0 + 1) * YS + r1] = Cr[mt][no][3] + bi1;
            }
        }
    }
    __syncthreads();

    // P4: per-column stats (pre-shift columns), 2 atomics per col per block
    {
        const int slot = blockIdx.x & (NSLOT - 1);
        for (int i = tid; i < VD; i += 256) {
            int v = i >> 6, d = i & 63;
            float s = 0.0f, q = 0.0f;
            #pragma unroll
            for (int tl = 0; tl < TT1; tl++) {
                float val = ys[d * YS + tl * Vv + v];
                s += val; q += val * val;
            }
            atomicAdd(&g_psum[slot][i], s);
            atomicAdd(&g_psq[slot][i],  q);
        }
    }

    // P5: shift_out-gathered transposed write: g_y[n][d][t0+tl][vout]
    {
        float* yb = g_y + ((size_t)n * Dd) * TV + t0 * Vv;
        for (int i = tid; i < Dd * R1; i += 256) {
            int d  = i / R1;
            int rr = i - d * R1;                 // tl*25 + vout
            int tl = rr / Vv;
            int vo = rr - tl * Vv;
            float val = ys[(int)sro[d * Vv + vo] + tl * Vv];
            yb[(size_t)d * TV + rr] = val;
        }
    }
}

// ---- k3: reduce slots at src column, fold shift_out/gamma/beta -> tables ----
__global__ void k3(const float* __restrict__ gamma, const float* __restrict__ beta,
                   const int* __restrict__ shift_out) {
    int j = blockIdx.x * blockDim.x + threadIdx.x;
    if (j >= VD) return;
    const int src = shift_out[j];
    float s = 0.0f, q = 0.0f;
    #pragma unroll
    for (int sl = 0; sl < NSLOT; sl++) { s += g_psum[sl][src]; q += g_psq[sl][src]; }
    const float inv_n = 1.0f / (float)NT;
    float mean = s * inv_n;
    float var  = q * inv_n - mean * mean;
    float sc   = gamma[j] * rsqrtf(var + BN_EPS);
    int v = j >> 6, d = j & 63;
    g_sclt[d * Vv + v] = sc;
    g_biat[d * Vv + v] = beta[j] - mean * sc;
}

// ---- k4: pure streaming affine + residual + relu over (n,d) planes ----
__global__ void __launch_bounds__(256) k4(const float* __restrict__ x0,
                                          float* __restrict__ out) {
    __shared__ float4 s4[Vv], b4[Vv];
    const int tid = threadIdx.x;
    const int d = blockIdx.x & 63;

    if (tid < Vv) {
        int m = tid;
        const float* sp = g_sclt + d * Vv;
        const float* bp = g_biat + d * Vv;
        int v0 = (4*m) % 25, v1 = (4*m+1) % 25, v2 = (4*m+2) % 25, v3 = (4*m+3) % 25;
        s4[m] = make_float4(sp[v0], sp[v1], sp[v2], sp[v3]);
        b4[m] = make_float4(bp[v0], bp[v1], bp[v2], bp[v3]);
    }
    __syncthreads();

    const size_t base = (size_t)blockIdx.x * TV;     // (n*64+d)*7500
    const float4* yp = (const float4*)(g_y + base);
    const float4* xp = (const float4*)(x0 + base);
    float4* op = (float4*)(out + base);

    #pragma unroll 2
    for (int i = tid; i < TV / 4; i += 256) {        // 1875 float4
        int m = i % 25;
        float4 y = yp[i];
        float4 x = xp[i];
        float4 s = s4[m];
        float4 bb = b4[m];
        float4 r;
        r.x = fmaxf(fmaf(y.x, s.x, bb.x) + x.x, 0.0f);
        r.y = fmaxf(fmaf(y.y, s.y, bb.y) + x.y, 0.0f);
        r.z = fmaxf(fmaf(y.z, s.z, bb.z) + x.z, 0.0f);
        r.w = fmaxf(fmaf(y.w, s.w, bb.w) + x.w, 0.0f);
        op[i] = r;
    }
}

extern "C" void kernel_launch(void* const* d_in, const int* in_sizes, int n_in,
                              void* d_out, int out_size) {
    const float* x0        = (const float*)d_in[0];
    const float* fm        = (const float*)d_in[1];
    const float* W         = (const float*)d_in[2];
    const float* b         = (const float*)d_in[3];
    const float* gamma     = (const float*)d_in[4];
    const float* beta      = (const float*)d_in[5];
    const int*   shift_in  = (const int*)d_in[6];
    const int*   shift_out = (const int*)d_in[7];
    float* out = (float*)d_out;

    const int smem1 = SM_TOT * 4;                    // 48512 B -> 4 CTAs/SM
    cudaFuncSetAttribute(kg, cudaFuncAttributeMaxDynamicSharedMemorySize, smem1);

    kprep<<<(NSLOT * VD + 255) / 256, 256>>>(fm, shift_in, shift_out, W);
    kg<<<NT / TT1, 256, smem1>>>(x0, b);
    k3<<<(VD + 255) / 256, 256>>>(gamma, beta, shift_out);
    k4<<<Nn * Dd, 256>>>(x0, out);
}